// round 6
// baseline (speedup 1.0000x reference)
#include <cuda_runtime.h>
#include <cuda_bf16.h>
#include <math.h>
#include <stdint.h>

#define D_K    2048
#define B_F    4096
#define C_C    2048
#define NUMR   2
#define NEARK  3
#define MAXIT  15
#define MARGINF 1.0f
#define IBIG   0x7FFFFFFF

// ---------------------------------------------------------------------------
// Device scratch
// ---------------------------------------------------------------------------
__device__ float g_Dfc[(size_t)B_F * C_C];   // 32 MB
__device__ float g_Dcc[(size_t)C_C * C_C];   // 16 MB
__device__ float g_fn[B_F];
__device__ float g_cn[C_C];
__device__ int4  g_near[C_C];
__device__ float g_hinge[B_F];
__device__ __nv_bfloat16 g_fh[(size_t)B_F * D_K];
__device__ __nv_bfloat16 g_fl[(size_t)B_F * D_K];
__device__ __nv_bfloat16 g_ch[(size_t)C_C * D_K];
__device__ __nv_bfloat16 g_cl[(size_t)C_C * D_K];

// ---------------------------------------------------------------------------
// Baseline-PTX helpers (sm_80+ only; plain sm_103 target has no tcgen05)
// ---------------------------------------------------------------------------
__device__ __forceinline__ uint32_t smem_u32(const void* p) {
    uint32_t a;
    asm("{ .reg .u64 t; cvta.to.shared.u64 t, %1; cvt.u32.u64 %0, t; }" : "=r"(a) : "l"(p));
    return a;
}
__device__ __forceinline__ void cp16(uint32_t s, const void* g) {
    asm volatile("cp.async.cg.shared.global [%0], [%1], 16;" :: "r"(s), "l"(g));
}
#define CP_COMMIT() asm volatile("cp.async.commit_group;" ::: "memory")
#define CP_WAIT1()  asm volatile("cp.async.wait_group 1;" ::: "memory")

__device__ __forceinline__ void ldsm4(uint32_t& r0, uint32_t& r1, uint32_t& r2, uint32_t& r3,
                                      uint32_t addr) {
    asm volatile("ldmatrix.sync.aligned.m8n8.x4.shared.b16 {%0,%1,%2,%3}, [%4];"
                 : "=r"(r0), "=r"(r1), "=r"(r2), "=r"(r3) : "r"(addr));
}
__device__ __forceinline__ void mma16816(float c[4], const uint32_t a[4],
                                         uint32_t b0, uint32_t b1) {
    asm volatile("mma.sync.aligned.m16n8k16.row.col.f32.bf16.bf16.f32 "
                 "{%0,%1,%2,%3}, {%4,%5,%6,%7}, {%8,%9}, {%0,%1,%2,%3};"
                 : "+f"(c[0]), "+f"(c[1]), "+f"(c[2]), "+f"(c[3])
                 : "r"(a[0]), "r"(a[1]), "r"(a[2]), "r"(a[3]), "r"(b0), "r"(b1));
}

// ---------------------------------------------------------------------------
// Fused fp32 -> (bf16 hi, bf16 lo) split + row squared-norm. One block per row.
// ---------------------------------------------------------------------------
__global__ void __launch_bounds__(256)
split_norm_k(const float* __restrict__ A, __nv_bfloat16* __restrict__ hi,
             __nv_bfloat16* __restrict__ lo, float* __restrict__ nrm) {
    const int row = blockIdx.x;
    const int tid = threadIdx.x;
    const float4* a = (const float4*)(A + (size_t)row * D_K);
    __nv_bfloat162* H = (__nv_bfloat162*)(hi + (size_t)row * D_K);
    __nv_bfloat162* L = (__nv_bfloat162*)(lo + (size_t)row * D_K);

    float s = 0.f;
#pragma unroll
    for (int j = 0; j < 2; j++) {
        const int i = tid + j * 256;         // float4 index (512 per row)
        float4 v = a[i];
        s = fmaf(v.x, v.x, s); s = fmaf(v.y, v.y, s);
        s = fmaf(v.z, v.z, s); s = fmaf(v.w, v.w, s);
        __nv_bfloat16 h0 = __float2bfloat16(v.x);
        __nv_bfloat16 h1 = __float2bfloat16(v.y);
        __nv_bfloat16 h2 = __float2bfloat16(v.z);
        __nv_bfloat16 h3 = __float2bfloat16(v.w);
        H[i * 2 + 0] = __nv_bfloat162(h0, h1);
        H[i * 2 + 1] = __nv_bfloat162(h2, h3);
        L[i * 2 + 0] = __nv_bfloat162(__float2bfloat16(v.x - __bfloat162float(h0)),
                                      __float2bfloat16(v.y - __bfloat162float(h1)));
        L[i * 2 + 1] = __nv_bfloat162(__float2bfloat16(v.z - __bfloat162float(h2)),
                                      __float2bfloat16(v.w - __bfloat162float(h3)));
    }
    __shared__ float red[256];
    red[tid] = s; __syncthreads();
    for (int st = 128; st > 0; st >>= 1) { if (tid < st) red[tid] += red[tid + st]; __syncthreads(); }
    if (tid == 0) nrm[row] = red[0];
}

// ---------------------------------------------------------------------------
// Merged tensor-core distance GEMM (both problems, one launch).
// Dout[m][n] = a2[m] + b2[n] - 2*(Ah+Al)_m.(Bh+Bl)_n, 3-term bf16 mma.sync.
// CTA tile 128x128, K-chunk 32, 3-stage cp.async ring, 1 sync/iter.
// blockIdx.x < 256 -> centers x centers; else features x centers.
// ---------------------------------------------------------------------------
#define KC     32
#define NIT    (D_K / KC)            // 64
#define PADW   40                    // smem row stride (bf16) -> 80 B
#define TILEB  (128 * PADW * 2)      // 10240 B
#define STAGEB (4 * TILEB)           // 40960 B
#define NSTG   3
#define SMEMB  (NSTG * STAGEB)       // 122880 B

__global__ void __launch_bounds__(256)
mma_gemm_all_k() {
    extern __shared__ char smem[];
    const uint32_t sb = smem_u32(smem);

    const int bx = blockIdx.x;
    const __nv_bfloat16 *Ah, *Al;
    const float *a2;
    float *Dout;
    int bm, bn;
    if (bx < 256) {                     // cc problem: 16x16 tiles
        bm = (bx >> 4) * 128; bn = (bx & 15) * 128;
        Ah = g_ch; Al = g_cl; a2 = g_cn; Dout = g_Dcc;
    } else {                            // fc problem: 32x16 tiles
        const int t = bx - 256;
        bm = (t >> 4) * 128; bn = (t & 15) * 128;
        Ah = g_fh; Al = g_fl; a2 = g_fn; Dout = g_Dfc;
    }
    const __nv_bfloat16* Bh = g_ch;
    const __nv_bfloat16* Bl = g_cl;
    const float* b2 = g_cn;

    const int tid  = threadIdx.x;
    const int lane = tid & 31;
    const int wid  = tid >> 5;
    const int wm   = wid & 1;
    const int wn   = wid >> 1;

    const __nv_bfloat16* gbase[4] = {
        Ah + (size_t)bm * D_K, Al + (size_t)bm * D_K,
        Bh + (size_t)bn * D_K, Bl + (size_t)bn * D_K };

    const int a_row = (lane & 15);
    const int a_ch  = lane >> 4;
    const uint32_t aoff = (uint32_t)((wm * 64 + a_row) * (PADW * 2) + a_ch * 16);
    const int b_row = (lane & 7) + ((lane >> 4) << 3);
    const int b_ch  = (lane >> 3) & 1;
    const uint32_t boff = (uint32_t)((wn * 32 + b_row) * (PADW * 2) + b_ch * 16);

    float acc[4][4][4];
#pragma unroll
    for (int i = 0; i < 4; i++)
#pragma unroll
        for (int j = 0; j < 4; j++)
#pragma unroll
            for (int q = 0; q < 4; q++) acc[i][j][q] = 0.f;

    auto load_stage = [&](int slot, int kc) {
        if (kc < NIT) {
            const int koff = kc * KC;
            const uint32_t sbase = sb + slot * STAGEB;
#pragma unroll
            for (int q = 0; q < 8; q++) {
                const int t   = q >> 1;
                const int rem = ((q & 1) << 8) + tid;
                const int row = rem >> 2;
                const int ch  = rem & 3;
                cp16(sbase + t * TILEB + row * (PADW * 2) + ch * 16,
                     gbase[t] + (size_t)row * D_K + koff + ch * 8);
            }
        }
        CP_COMMIT();   // unconditional: keeps group count exact at the tail
    };

    load_stage(0, 0);
    load_stage(1, 1);

    for (int kc = 0; kc < NIT; kc++) {
        CP_WAIT1();          // stage kc complete (<=1 group pending after wait)
        __syncthreads();     // all warps done reading slot (kc+2)%3 (iter kc-1)
        load_stage((kc + 2) % NSTG, kc + 2);

        const uint32_t st = sb + (kc % NSTG) * STAGEB;
#pragma unroll
        for (int ks = 0; ks < 2; ks++) {
            uint32_t ah[4][4], al[4][4], bh[2][4], bl[2][4];
#pragma unroll
            for (int mf = 0; mf < 4; mf++) {
                const uint32_t ao = aoff + mf * 16 * (PADW * 2) + ks * 32;
                ldsm4(ah[mf][0], ah[mf][1], ah[mf][2], ah[mf][3], st + 0 * TILEB + ao);
                ldsm4(al[mf][0], al[mf][1], al[mf][2], al[mf][3], st + 1 * TILEB + ao);
            }
#pragma unroll
            for (int nf2 = 0; nf2 < 2; nf2++) {
                const uint32_t bo = boff + nf2 * 16 * (PADW * 2) + ks * 32;
                ldsm4(bh[nf2][0], bh[nf2][1], bh[nf2][2], bh[nf2][3], st + 2 * TILEB + bo);
                ldsm4(bl[nf2][0], bl[nf2][1], bl[nf2][2], bl[nf2][3], st + 3 * TILEB + bo);
            }
#pragma unroll
            for (int mf = 0; mf < 4; mf++) {
#pragma unroll
                for (int nf = 0; nf < 4; nf++) {
                    const int h = nf >> 1, o = (nf & 1) << 1;
                    mma16816(acc[mf][nf], ah[mf], bh[h][o], bh[h][o + 1]);
                    mma16816(acc[mf][nf], ah[mf], bl[h][o], bl[h][o + 1]);
                    mma16816(acc[mf][nf], al[mf], bh[h][o], bh[h][o + 1]);
                }
            }
        }
    }

    // epilogue: d2 = a2[m] + b2[n] - 2*dot
#pragma unroll
    for (int mf = 0; mf < 4; mf++) {
        const int r0  = bm + wm * 64 + mf * 16 + (lane >> 2);
        const float am0 = a2[r0];
        const float am1 = a2[r0 + 8];
        float* out0 = Dout + (size_t)r0 * C_C;
        float* out1 = Dout + (size_t)(r0 + 8) * C_C;
#pragma unroll
        for (int nf = 0; nf < 4; nf++) {
            const int n = bn + wn * 32 + nf * 8 + ((lane & 3) << 1);
            const float b0 = b2[n], b1 = b2[n + 1];
            float2 p0, p1;
            p0.x = fmaf(-2.f, acc[mf][nf][0], am0 + b0);
            p0.y = fmaf(-2.f, acc[mf][nf][1], am0 + b1);
            p1.x = fmaf(-2.f, acc[mf][nf][2], am1 + b0);
            p1.y = fmaf(-2.f, acc[mf][nf][3], am1 + b1);
            *(float2*)(out0 + n) = p0;
            *(float2*)(out1 + n) = p1;
        }
    }
}

// ---------------------------------------------------------------------------
// Per-center 3-NN (single pass + merge)
// ---------------------------------------------------------------------------
__global__ void near3_k() {
    const int c0  = blockIdx.x;
    const int tid = threadIdx.x;
    const float* row = g_Dcc + (size_t)c0 * C_C;

    float t0 = INFINITY, t1 = INFINITY, t2 = INFINITY;
    int   i0 = IBIG,     i1 = IBIG,     i2 = IBIG;
#pragma unroll
    for (int j = 0; j < C_C / 256; j++) {
        const int c = tid + j * 256;
        const float v = row[c];
        if (v < t2 || (v == t2 && c < i2)) {
            t2 = v; i2 = c;
            if (t2 < t1 || (t2 == t1 && i2 < i1)) {
                float tv = t1; int ti = i1; t1 = t2; i1 = i2; t2 = tv; i2 = ti;
                if (t1 < t0 || (t1 == t0 && i1 < i0)) {
                    tv = t0; ti = i0; t0 = t1; i0 = i1; t1 = tv; i1 = ti;
                }
            }
        }
    }
    __shared__ float sval[3 * 256];
    __shared__ int   sidx[3 * 256];
    sval[tid] = t0;       sidx[tid] = i0;
    sval[tid + 256] = t1; sidx[tid + 256] = i1;
    sval[tid + 512] = t2; sidx[tid + 512] = i2;
    __syncthreads();

    __shared__ float rv[256];
    __shared__ int   ri[256];
    __shared__ int   out3[3];
    for (int it = 0; it < NEARK; it++) {
        float bv = sval[tid]; int bi = sidx[tid];
#pragma unroll
        for (int k = 1; k < 3; k++) {
            float v = sval[tid + k * 256]; int ii = sidx[tid + k * 256];
            if (v < bv || (v == bv && ii < bi)) { bv = v; bi = ii; }
        }
        rv[tid] = bv; ri[tid] = bi;
        __syncthreads();
        for (int st = 128; st > 0; st >>= 1) {
            if (tid < st) {
                float v2 = rv[tid + st]; int j2 = ri[tid + st];
                if (v2 < rv[tid] || (v2 == rv[tid] && j2 < ri[tid])) { rv[tid] = v2; ri[tid] = j2; }
            }
            __syncthreads();
        }
        const float wv = rv[0]; const int wi = ri[0];
        if (tid == 0) out3[it] = wi;
#pragma unroll
        for (int k = 0; k < 3; k++) {
            if (sval[tid + k * 256] == wv && sidx[tid + k * 256] == wi) {
                sval[tid + k * 256] = INFINITY; sidx[tid + k * 256] = IBIG;
            }
        }
        __syncthreads();
    }
    if (tid == 0) { int4 p; p.x = out3[0]; p.y = out3[1]; p.z = out3[2]; p.w = 0; g_near[c0] = p; }
}

// ---------------------------------------------------------------------------
// Per-feature-row selection (non-iterative)
// ---------------------------------------------------------------------------
__global__ void select_k() {
    const int b   = blockIdx.x;
    const int l   = b / NUMR;
    const int tid = threadIdx.x;
    const float* row = g_Dfc + (size_t)b * C_C;

    float v[C_C / 256];
    float bv = INFINITY; int bi = IBIG;
#pragma unroll
    for (int j = 0; j < C_C / 256; j++) {
        const int c = tid + j * 256;
        const float d = row[c];
        v[j] = d;
        const int4 nr = g_near[c];
        const bool tr = (c != l) && (nr.x != l) && (nr.y != l) && (nr.z != l);
        if (tr && (d < bv || (d == bv && c < bi))) { bv = d; bi = c; }
    }
    __shared__ float rv[256];
    __shared__ int   ri[256];
    rv[tid] = bv; ri[tid] = bi;
    __syncthreads();
    for (int st = 128; st > 0; st >>= 1) {
        if (tid < st) {
            float v2 = rv[tid + st]; int i2 = ri[tid + st];
            if (v2 < rv[tid] || (v2 == rv[tid] && i2 < ri[tid])) { rv[tid] = v2; ri[tid] = i2; }
        }
        __syncthreads();
    }
    const float Tval = rv[0]; const int Tidx = ri[0];
    __syncthreads();

    int cnt = 0;
#pragma unroll
    for (int j = 0; j < C_C / 256; j++) {
        const int c = tid + j * 256;
        if (c != l && (v[j] < Tval || (v[j] == Tval && c < Tidx))) cnt++;
    }
    __shared__ int rc[256];
    rc[tid] = cnt;
    __syncthreads();
    for (int st = 128; st > 0; st >>= 1) { if (tid < st) rc[tid] += rc[tid + st]; __syncthreads(); }

    if (tid == 0) {
        const bool found = (Tidx < C_C) && (rc[0] <= MAXIT - 1);
        const float same = sqrtf(fmaxf(row[l], 0.f));
        const float md   = found ? sqrtf(fmaxf(Tval, 0.f)) : 0.f;
        g_hinge[b] = fmaxf(MARGINF + same - md, 0.f);
    }
}

// ---------------------------------------------------------------------------
__global__ void reduce_k(float* __restrict__ out) {
    const int tid = threadIdx.x;
    __shared__ float red[256];
    float s = 0.f;
    for (int i = tid; i < B_F; i += 256) s += g_hinge[i];
    red[tid] = s;
    __syncthreads();
    for (int st = 128; st > 0; st >>= 1) { if (tid < st) red[tid] += red[tid + st]; __syncthreads(); }
    if (tid == 0) out[0] = red[0] * (1.0f / (float)B_F);
}

// ---------------------------------------------------------------------------
extern "C" void kernel_launch(void* const* d_in, const int* in_sizes, int n_in,
                              void* d_out, int out_size) {
    (void)in_sizes; (void)n_in; (void)out_size;
    const float* feat = (const float*)d_in[0];
    const float* cent = (const float*)d_in[1];
    float* out = (float*)d_out;

    cudaFuncSetAttribute(mma_gemm_all_k, cudaFuncAttributeMaxDynamicSharedMemorySize, SMEMB);

    __nv_bfloat16 *fh, *fl, *ch, *cl;
    float *fn, *cn;
    cudaGetSymbolAddress((void**)&fh, g_fh);
    cudaGetSymbolAddress((void**)&fl, g_fl);
    cudaGetSymbolAddress((void**)&ch, g_ch);
    cudaGetSymbolAddress((void**)&cl, g_cl);
    cudaGetSymbolAddress((void**)&fn, g_fn);
    cudaGetSymbolAddress((void**)&cn, g_cn);

    split_norm_k<<<B_F, 256>>>(feat, fh, fl, fn);
    split_norm_k<<<C_C, 256>>>(cent, ch, cl, cn);

    mma_gemm_all_k<<<768, 256, SMEMB>>>();

    near3_k<<<C_C, 256>>>();
    select_k<<<B_F, 256>>>();
    reduce_k<<<1, 256>>>(out);
}

// round 7
// speedup vs baseline: 1.3317x; 1.3317x over previous
#include <cuda_runtime.h>
#include <cuda_bf16.h>
#include <math.h>
#include <stdint.h>

#define D_K    2048
#define B_F    4096
#define C_C    2048
#define NUMR   2
#define NEARK  3
#define MAXIT  15
#define MARGINF 1.0f
#define IBIG   0x7FFFFFFF

// ---------------------------------------------------------------------------
// Device scratch
// ---------------------------------------------------------------------------
__device__ float g_Dfc[(size_t)B_F * C_C];   // 32 MB
__device__ float g_Dcc[(size_t)C_C * C_C];   // 16 MB
__device__ float g_fn[B_F];
__device__ float g_cn[C_C];
__device__ int4  g_near[C_C];
__device__ float g_hinge[B_F];
__device__ __nv_bfloat16 g_fh[(size_t)B_F * D_K];
__device__ __nv_bfloat16 g_fl[(size_t)B_F * D_K];
__device__ __nv_bfloat16 g_ch[(size_t)C_C * D_K];
__device__ __nv_bfloat16 g_cl[(size_t)C_C * D_K];

// ---------------------------------------------------------------------------
// Baseline-PTX helpers (sm_80+ only; plain sm_103 target has no tcgen05)
// ---------------------------------------------------------------------------
__device__ __forceinline__ uint32_t smem_u32(const void* p) {
    uint32_t a;
    asm("{ .reg .u64 t; cvta.to.shared.u64 t, %1; cvt.u32.u64 %0, t; }" : "=r"(a) : "l"(p));
    return a;
}
__device__ __forceinline__ void cp16(uint32_t s, const void* g) {
    asm volatile("cp.async.cg.shared.global [%0], [%1], 16;" :: "r"(s), "l"(g));
}
#define CP_COMMIT() asm volatile("cp.async.commit_group;" ::: "memory")
#define CP_WAIT1()  asm volatile("cp.async.wait_group 1;" ::: "memory")
#define CP_WAIT0()  asm volatile("cp.async.wait_group 0;" ::: "memory")

__device__ __forceinline__ void ldsm4(uint32_t& r0, uint32_t& r1, uint32_t& r2, uint32_t& r3,
                                      uint32_t addr) {
    asm volatile("ldmatrix.sync.aligned.m8n8.x4.shared.b16 {%0,%1,%2,%3}, [%4];"
                 : "=r"(r0), "=r"(r1), "=r"(r2), "=r"(r3) : "r"(addr));
}
__device__ __forceinline__ void mma16816(float c[4], const uint32_t a[4],
                                         uint32_t b0, uint32_t b1) {
    asm volatile("mma.sync.aligned.m16n8k16.row.col.f32.bf16.bf16.f32 "
                 "{%0,%1,%2,%3}, {%4,%5,%6,%7}, {%8,%9}, {%0,%1,%2,%3};"
                 : "+f"(c[0]), "+f"(c[1]), "+f"(c[2]), "+f"(c[3])
                 : "r"(a[0]), "r"(a[1]), "r"(a[2]), "r"(a[3]), "r"(b0), "r"(b1));
}

// ---------------------------------------------------------------------------
// Fused fp32 -> (bf16 hi, bf16 lo) split + row squared-norm. One block per row.
// ---------------------------------------------------------------------------
__global__ void __launch_bounds__(256)
split_norm_k(const float* __restrict__ A, __nv_bfloat16* __restrict__ hi,
             __nv_bfloat16* __restrict__ lo, float* __restrict__ nrm) {
    const int row = blockIdx.x;
    const int tid = threadIdx.x;
    const float4* a = (const float4*)(A + (size_t)row * D_K);
    __nv_bfloat162* H = (__nv_bfloat162*)(hi + (size_t)row * D_K);
    __nv_bfloat162* L = (__nv_bfloat162*)(lo + (size_t)row * D_K);

    float s = 0.f;
#pragma unroll
    for (int j = 0; j < 2; j++) {
        const int i = tid + j * 256;
        float4 v = a[i];
        s = fmaf(v.x, v.x, s); s = fmaf(v.y, v.y, s);
        s = fmaf(v.z, v.z, s); s = fmaf(v.w, v.w, s);
        __nv_bfloat16 h0 = __float2bfloat16(v.x);
        __nv_bfloat16 h1 = __float2bfloat16(v.y);
        __nv_bfloat16 h2 = __float2bfloat16(v.z);
        __nv_bfloat16 h3 = __float2bfloat16(v.w);
        H[i * 2 + 0] = __nv_bfloat162(h0, h1);
        H[i * 2 + 1] = __nv_bfloat162(h2, h3);
        L[i * 2 + 0] = __nv_bfloat162(__float2bfloat16(v.x - __bfloat162float(h0)),
                                      __float2bfloat16(v.y - __bfloat162float(h1)));
        L[i * 2 + 1] = __nv_bfloat162(__float2bfloat16(v.z - __bfloat162float(h2)),
                                      __float2bfloat16(v.w - __bfloat162float(h3)));
    }
    __shared__ float red[256];
    red[tid] = s; __syncthreads();
    for (int st = 128; st > 0; st >>= 1) { if (tid < st) red[tid] += red[tid + st]; __syncthreads(); }
    if (tid == 0) nrm[row] = red[0];
}

// ---------------------------------------------------------------------------
// Merged tensor-core distance GEMM, one launch, 2-stage cp.async double buffer
// (2 CTAs/SM). cc problem computes only upper-triangular tiles and mirrors.
//   Dout[m][n] = a2[m] + b2[n] - 2*(Ah+Al)_m.(Bh+Bl)_n   (3-term bf16)
// ---------------------------------------------------------------------------
#define KC     32
#define NIT    (D_K / KC)            // 64
#define PADW   40                    // smem row stride (bf16) -> 80 B
#define TILEB  (128 * PADW * 2)      // 10240 B
#define STAGEB (4 * TILEB)           // 40960 B
#define SMEMB  (2 * STAGEB)          // 81920 B -> 2 CTAs/SM
#define NCCT   136                   // 16*17/2 upper-tri cc tiles
#define NGRID  (NCCT + 512)          // 648

__global__ void __launch_bounds__(256)
mma_gemm_all_k() {
    extern __shared__ char smem[];
    const uint32_t sb = smem_u32(smem);

    const int bx = blockIdx.x;
    const __nv_bfloat16 *Ah, *Al;
    const float *a2;
    float *Dout;
    int bm, bn;
    bool mirror = false;
    if (bx < NCCT) {                    // cc upper triangle
        int r = 0, rem = bx;
        while (rem >= 16 - r) { rem -= 16 - r; r++; }
        bm = r * 128; bn = (r + rem) * 128;
        mirror = (rem != 0);
        Ah = g_ch; Al = g_cl; a2 = g_cn; Dout = g_Dcc;
    } else {                            // fc: 32x16 tiles
        const int t = bx - NCCT;
        bm = (t >> 4) * 128; bn = (t & 15) * 128;
        Ah = g_fh; Al = g_fl; a2 = g_fn; Dout = g_Dfc;
    }
    const __nv_bfloat16* Bh = g_ch;
    const __nv_bfloat16* Bl = g_cl;
    const float* b2 = g_cn;

    const int tid  = threadIdx.x;
    const int lane = tid & 31;
    const int wid  = tid >> 5;
    const int wm   = wid & 1;
    const int wn   = wid >> 1;

    const __nv_bfloat16* gbase[4] = {
        Ah + (size_t)bm * D_K, Al + (size_t)bm * D_K,
        Bh + (size_t)bn * D_K, Bl + (size_t)bn * D_K };

    const int a_row = (lane & 15);
    const int a_ch  = lane >> 4;
    const uint32_t aoff = (uint32_t)((wm * 64 + a_row) * (PADW * 2) + a_ch * 16);
    const int b_row = (lane & 7) + ((lane >> 4) << 3);
    const int b_ch  = (lane >> 3) & 1;
    const uint32_t boff = (uint32_t)((wn * 32 + b_row) * (PADW * 2) + b_ch * 16);

    float acc[4][4][4];
#pragma unroll
    for (int i = 0; i < 4; i++)
#pragma unroll
        for (int j = 0; j < 4; j++)
#pragma unroll
            for (int q = 0; q < 4; q++) acc[i][j][q] = 0.f;

    auto load_stage = [&](int buf, int kc) {
        const int koff = kc * KC;
        const uint32_t sbase = sb + buf * STAGEB;
#pragma unroll
        for (int q = 0; q < 8; q++) {
            const int t   = q >> 1;
            const int rem = ((q & 1) << 8) + tid;
            const int row = rem >> 2;
            const int ch  = rem & 3;
            cp16(sbase + t * TILEB + row * (PADW * 2) + ch * 16,
                 gbase[t] + (size_t)row * D_K + koff + ch * 8);
        }
        CP_COMMIT();
    };

    load_stage(0, 0);

    for (int kc = 0; kc < NIT; kc++) {
        if (kc + 1 < NIT) load_stage((kc + 1) & 1, kc + 1);
        if (kc + 1 < NIT) CP_WAIT1(); else CP_WAIT0();
        __syncthreads();

        const uint32_t st = sb + (kc & 1) * STAGEB;
#pragma unroll
        for (int ks = 0; ks < 2; ks++) {
            uint32_t ah[4][4], al[4][4], bh[2][4], bl[2][4];
#pragma unroll
            for (int mf = 0; mf < 4; mf++) {
                const uint32_t ao = aoff + mf * 16 * (PADW * 2) + ks * 32;
                ldsm4(ah[mf][0], ah[mf][1], ah[mf][2], ah[mf][3], st + 0 * TILEB + ao);
                ldsm4(al[mf][0], al[mf][1], al[mf][2], al[mf][3], st + 1 * TILEB + ao);
            }
#pragma unroll
            for (int nf2 = 0; nf2 < 2; nf2++) {
                const uint32_t bo = boff + nf2 * 16 * (PADW * 2) + ks * 32;
                ldsm4(bh[nf2][0], bh[nf2][1], bh[nf2][2], bh[nf2][3], st + 2 * TILEB + bo);
                ldsm4(bl[nf2][0], bl[nf2][1], bl[nf2][2], bl[nf2][3], st + 3 * TILEB + bo);
            }
#pragma unroll
            for (int mf = 0; mf < 4; mf++) {
#pragma unroll
                for (int nf = 0; nf < 4; nf++) {
                    const int h = nf >> 1, o = (nf & 1) << 1;
                    mma16816(acc[mf][nf], ah[mf], bh[h][o], bh[h][o + 1]);
                    mma16816(acc[mf][nf], ah[mf], bl[h][o], bl[h][o + 1]);
                    mma16816(acc[mf][nf], al[mf], bh[h][o], bh[h][o + 1]);
                }
            }
        }
        __syncthreads();
    }

    // epilogue: d2 = a2[m] + b2[n] - 2*dot ; mirror for cc off-diagonal tiles
#pragma unroll
    for (int mf = 0; mf < 4; mf++) {
        const int r0  = bm + wm * 64 + mf * 16 + (lane >> 2);
        const float am0 = a2[r0];
        const float am1 = a2[r0 + 8];
        float* out0 = Dout + (size_t)r0 * C_C;
        float* out1 = Dout + (size_t)(r0 + 8) * C_C;
#pragma unroll
        for (int nf = 0; nf < 4; nf++) {
            const int n = bn + wn * 32 + nf * 8 + ((lane & 3) << 1);
            const float b0 = b2[n], b1 = b2[n + 1];
            float2 p0, p1;
            p0.x = fmaf(-2.f, acc[mf][nf][0], am0 + b0);
            p0.y = fmaf(-2.f, acc[mf][nf][1], am0 + b1);
            p1.x = fmaf(-2.f, acc[mf][nf][2], am1 + b0);
            p1.y = fmaf(-2.f, acc[mf][nf][3], am1 + b1);
            *(float2*)(out0 + n) = p0;
            *(float2*)(out1 + n) = p1;
            if (mirror) {
                float* t0 = Dout + (size_t)n * C_C;
                float* t1 = Dout + (size_t)(n + 1) * C_C;
                t0[r0]     = p0.x;  t1[r0]     = p0.y;
                t0[r0 + 8] = p1.x;  t1[r0 + 8] = p1.y;
            }
        }
    }
}

// ---------------------------------------------------------------------------
// Per-center 3-NN (single pass + merge)
// ---------------------------------------------------------------------------
__global__ void near3_k() {
    const int c0  = blockIdx.x;
    const int tid = threadIdx.x;
    const float* row = g_Dcc + (size_t)c0 * C_C;

    float t0 = INFINITY, t1 = INFINITY, t2 = INFINITY;
    int   i0 = IBIG,     i1 = IBIG,     i2 = IBIG;
#pragma unroll
    for (int j = 0; j < C_C / 256; j++) {
        const int c = tid + j * 256;
        const float v = row[c];
        if (v < t2 || (v == t2 && c < i2)) {
            t2 = v; i2 = c;
            if (t2 < t1 || (t2 == t1 && i2 < i1)) {
                float tv = t1; int ti = i1; t1 = t2; i1 = i2; t2 = tv; i2 = ti;
                if (t1 < t0 || (t1 == t0 && i1 < i0)) {
                    tv = t0; ti = i0; t0 = t1; i0 = i1; t1 = tv; i1 = ti;
                }
            }
        }
    }
    __shared__ float sval[3 * 256];
    __shared__ int   sidx[3 * 256];
    sval[tid] = t0;       sidx[tid] = i0;
    sval[tid + 256] = t1; sidx[tid + 256] = i1;
    sval[tid + 512] = t2; sidx[tid + 512] = i2;
    __syncthreads();

    __shared__ float rv[256];
    __shared__ int   ri[256];
    __shared__ int   out3[3];
    for (int it = 0; it < NEARK; it++) {
        float bv = sval[tid]; int bi = sidx[tid];
#pragma unroll
        for (int k = 1; k < 3; k++) {
            float v = sval[tid + k * 256]; int ii = sidx[tid + k * 256];
            if (v < bv || (v == bv && ii < bi)) { bv = v; bi = ii; }
        }
        rv[tid] = bv; ri[tid] = bi;
        __syncthreads();
        for (int st = 128; st > 0; st >>= 1) {
            if (tid < st) {
                float v2 = rv[tid + st]; int j2 = ri[tid + st];
                if (v2 < rv[tid] || (v2 == rv[tid] && j2 < ri[tid])) { rv[tid] = v2; ri[tid] = j2; }
            }
            __syncthreads();
        }
        const float wv = rv[0]; const int wi = ri[0];
        if (tid == 0) out3[it] = wi;
#pragma unroll
        for (int k = 0; k < 3; k++) {
            if (sval[tid + k * 256] == wv && sidx[tid + k * 256] == wi) {
                sval[tid + k * 256] = INFINITY; sidx[tid + k * 256] = IBIG;
            }
        }
        __syncthreads();
    }
    if (tid == 0) { int4 p; p.x = out3[0]; p.y = out3[1]; p.z = out3[2]; p.w = 0; g_near[c0] = p; }
}

// ---------------------------------------------------------------------------
// Per-feature-row selection (non-iterative)
// ---------------------------------------------------------------------------
__global__ void select_k() {
    const int b   = blockIdx.x;
    const int l   = b / NUMR;
    const int tid = threadIdx.x;
    const float* row = g_Dfc + (size_t)b * C_C;

    float v[C_C / 256];
    float bv = INFINITY; int bi = IBIG;
#pragma unroll
    for (int j = 0; j < C_C / 256; j++) {
        const int c = tid + j * 256;
        const float d = row[c];
        v[j] = d;
        const int4 nr = g_near[c];
        const bool tr = (c != l) && (nr.x != l) && (nr.y != l) && (nr.z != l);
        if (tr && (d < bv || (d == bv && c < bi))) { bv = d; bi = c; }
    }
    __shared__ float rv[256];
    __shared__ int   ri[256];
    rv[tid] = bv; ri[tid] = bi;
    __syncthreads();
    for (int st = 128; st > 0; st >>= 1) {
        if (tid < st) {
            float v2 = rv[tid + st]; int i2 = ri[tid + st];
            if (v2 < rv[tid] || (v2 == rv[tid] && i2 < ri[tid])) { rv[tid] = v2; ri[tid] = i2; }
        }
        __syncthreads();
    }
    const float Tval = rv[0]; const int Tidx = ri[0];
    __syncthreads();

    int cnt = 0;
#pragma unroll
    for (int j = 0; j < C_C / 256; j++) {
        const int c = tid + j * 256;
        if (c != l && (v[j] < Tval || (v[j] == Tval && c < Tidx))) cnt++;
    }
    __shared__ int rc[256];
    rc[tid] = cnt;
    __syncthreads();
    for (int st = 128; st > 0; st >>= 1) { if (tid < st) rc[tid] += rc[tid + st]; __syncthreads(); }

    if (tid == 0) {
        const bool found = (Tidx < C_C) && (rc[0] <= MAXIT - 1);
        const float same = sqrtf(fmaxf(row[l], 0.f));
        const float md   = found ? sqrtf(fmaxf(Tval, 0.f)) : 0.f;
        g_hinge[b] = fmaxf(MARGINF + same - md, 0.f);
    }
}

// ---------------------------------------------------------------------------
__global__ void reduce_k(float* __restrict__ out) {
    const int tid = threadIdx.x;
    __shared__ float red[256];
    float s = 0.f;
    for (int i = tid; i < B_F; i += 256) s += g_hinge[i];
    red[tid] = s;
    __syncthreads();
    for (int st = 128; st > 0; st >>= 1) { if (tid < st) red[tid] += red[tid + st]; __syncthreads(); }
    if (tid == 0) out[0] = red[0] * (1.0f / (float)B_F);
}

// ---------------------------------------------------------------------------
extern "C" void kernel_launch(void* const* d_in, const int* in_sizes, int n_in,
                              void* d_out, int out_size) {
    (void)in_sizes; (void)n_in; (void)out_size;
    const float* feat = (const float*)d_in[0];
    const float* cent = (const float*)d_in[1];
    float* out = (float*)d_out;

    cudaFuncSetAttribute(mma_gemm_all_k, cudaFuncAttributeMaxDynamicSharedMemorySize, SMEMB);

    __nv_bfloat16 *fh, *fl, *ch, *cl;
    float *fn, *cn;
    cudaGetSymbolAddress((void**)&fh, g_fh);
    cudaGetSymbolAddress((void**)&fl, g_fl);
    cudaGetSymbolAddress((void**)&ch, g_ch);
    cudaGetSymbolAddress((void**)&cl, g_cl);
    cudaGetSymbolAddress((void**)&fn, g_fn);
    cudaGetSymbolAddress((void**)&cn, g_cn);

    split_norm_k<<<B_F, 256>>>(feat, fh, fl, fn);
    split_norm_k<<<C_C, 256>>>(cent, ch, cl, cn);

    mma_gemm_all_k<<<NGRID, 256, SMEMB>>>();

    near3_k<<<C_C, 256>>>();
    select_k<<<B_F, 256>>>();
    reduce_k<<<1, 256>>>(out);
}

// round 9
// speedup vs baseline: 1.3574x; 1.0193x over previous
#include <cuda_runtime.h>
#include <cuda_bf16.h>
#include <math.h>
#include <stdint.h>

#define D_K    2048
#define B_F    4096
#define C_C    2048
#define NUMR   2
#define NEARK  3
#define MAXIT  15
#define MARGINF 1.0f
#define IBIG   0x7FFFFFFF

// ---------------------------------------------------------------------------
// Device scratch
// ---------------------------------------------------------------------------
__device__ float g_Dfc[(size_t)B_F * C_C];   // 32 MB
__device__ float g_Dcc[(size_t)C_C * C_C];   // 16 MB
__device__ float g_fn[B_F];
__device__ float g_cn[C_C];
__device__ int4  g_near[C_C];
__device__ float g_hinge[B_F];
__device__ __nv_bfloat16 g_fh[(size_t)B_F * D_K];
__device__ __nv_bfloat16 g_fl[(size_t)B_F * D_K];
__device__ __nv_bfloat16 g_ch[(size_t)C_C * D_K];
__device__ __nv_bfloat16 g_cl[(size_t)C_C * D_K];

// ---------------------------------------------------------------------------
// Baseline-PTX helpers (sm_80+ only; plain sm_103 target has no tcgen05)
// ---------------------------------------------------------------------------
__device__ __forceinline__ uint32_t smem_u32(const void* p) {
    uint32_t a;
    asm("{ .reg .u64 t; cvta.to.shared.u64 t, %1; cvt.u32.u64 %0, t; }" : "=r"(a) : "l"(p));
    return a;
}
__device__ __forceinline__ void cp16(uint32_t s, const void* g) {
    asm volatile("cp.async.cg.shared.global [%0], [%1], 16;" :: "r"(s), "l"(g));
}
#define CP_COMMIT() asm volatile("cp.async.commit_group;" ::: "memory")
#define CP_WAIT1()  asm volatile("cp.async.wait_group 1;" ::: "memory")
#define CP_WAIT0()  asm volatile("cp.async.wait_group 0;" ::: "memory")

__device__ __forceinline__ void ldsm4(uint32_t& r0, uint32_t& r1, uint32_t& r2, uint32_t& r3,
                                      uint32_t addr) {
    asm volatile("ldmatrix.sync.aligned.m8n8.x4.shared.b16 {%0,%1,%2,%3}, [%4];"
                 : "=r"(r0), "=r"(r1), "=r"(r2), "=r"(r3) : "r"(addr));
}
__device__ __forceinline__ void mma16816(float c[4], const uint32_t a[4],
                                         uint32_t b0, uint32_t b1) {
    asm volatile("mma.sync.aligned.m16n8k16.row.col.f32.bf16.bf16.f32 "
                 "{%0,%1,%2,%3}, {%4,%5,%6,%7}, {%8,%9}, {%0,%1,%2,%3};"
                 : "+f"(c[0]), "+f"(c[1]), "+f"(c[2]), "+f"(c[3])
                 : "r"(a[0]), "r"(a[1]), "r"(a[2]), "r"(a[3]), "r"(b0), "r"(b1));
}

// ---------------------------------------------------------------------------
// Fused fp32 -> (bf16 hi, bf16 lo) split + row squared-norm, one merged launch.
// blockIdx < B_F -> feature row; else center row.
// ---------------------------------------------------------------------------
__global__ void __launch_bounds__(256)
split_norm_all_k(const float* __restrict__ F, const float* __restrict__ Cn) {
    const int bx = blockIdx.x;
    const float* A;
    __nv_bfloat16 *hi, *lo;
    float* nrm;
    int row;
    if (bx < B_F) { row = bx;       A = F;  hi = g_fh; lo = g_fl; nrm = g_fn; }
    else          { row = bx - B_F; A = Cn; hi = g_ch; lo = g_cl; nrm = g_cn; }

    const int tid = threadIdx.x;
    const float4* a = (const float4*)(A + (size_t)row * D_K);
    __nv_bfloat162* H = (__nv_bfloat162*)(hi + (size_t)row * D_K);
    __nv_bfloat162* L = (__nv_bfloat162*)(lo + (size_t)row * D_K);

    float s = 0.f;
#pragma unroll
    for (int j = 0; j < 2; j++) {
        const int i = tid + j * 256;
        float4 v = a[i];
        s = fmaf(v.x, v.x, s); s = fmaf(v.y, v.y, s);
        s = fmaf(v.z, v.z, s); s = fmaf(v.w, v.w, s);
        __nv_bfloat16 h0 = __float2bfloat16(v.x);
        __nv_bfloat16 h1 = __float2bfloat16(v.y);
        __nv_bfloat16 h2 = __float2bfloat16(v.z);
        __nv_bfloat16 h3 = __float2bfloat16(v.w);
        H[i * 2 + 0] = __nv_bfloat162(h0, h1);
        H[i * 2 + 1] = __nv_bfloat162(h2, h3);
        L[i * 2 + 0] = __nv_bfloat162(__float2bfloat16(v.x - __bfloat162float(h0)),
                                      __float2bfloat16(v.y - __bfloat162float(h1)));
        L[i * 2 + 1] = __nv_bfloat162(__float2bfloat16(v.z - __bfloat162float(h2)),
                                      __float2bfloat16(v.w - __bfloat162float(h3)));
    }
    __shared__ float red[256];
    red[tid] = s; __syncthreads();
    for (int st = 128; st > 0; st >>= 1) { if (tid < st) red[tid] += red[tid + st]; __syncthreads(); }
    if (tid == 0) nrm[row] = red[0];
}

// ---------------------------------------------------------------------------
// Merged tensor-core distance GEMM. CTA tile 128x128, 4 warps of 64x64 each,
// 128 threads, 2-stage cp.async, 2 CTAs/SM. cc computes upper-tri + mirror.
// MMA:LDSM ratio 6:1 (was 4:1); terms ordered to avoid same-acc chains.
// ---------------------------------------------------------------------------
#define KC     32
#define NIT    (D_K / KC)            // 64
#define PADW   40
#define ROWB   (PADW * 2)            // 80 B
#define TILEB  (128 * ROWB)          // 10240 B
#define STAGEB (4 * TILEB)           // 40960 B
#define SMEMB  (2 * STAGEB)          // 81920 B -> 2 CTAs/SM
#define NCCT   136
#define NGRID  (NCCT + 512)          // 648

__global__ void __launch_bounds__(128, 2)
mma_gemm_all_k() {
    extern __shared__ char smem[];
    const uint32_t sb = smem_u32(smem);

    const int bx = blockIdx.x;
    const __nv_bfloat16 *Ah, *Al;
    const float *a2;
    float *Dout;
    int bm, bn;
    bool mirror = false;
    if (bx < NCCT) {
        int r = 0, rem = bx;
        while (rem >= 16 - r) { rem -= 16 - r; r++; }
        bm = r * 128; bn = (r + rem) * 128;
        mirror = (rem != 0);
        Ah = g_ch; Al = g_cl; a2 = g_cn; Dout = g_Dcc;
    } else {
        const int t = bx - NCCT;
        bm = (t >> 4) * 128; bn = (t & 15) * 128;
        Ah = g_fh; Al = g_fl; a2 = g_fn; Dout = g_Dfc;
    }
    const __nv_bfloat16* Bh = g_ch;
    const __nv_bfloat16* Bl = g_cl;
    const float* b2 = g_cn;

    const int tid  = threadIdx.x;
    const int lane = tid & 31;
    const int wid  = tid >> 5;
    const int wm   = wid & 1;        // 2 m-tiles of 64
    const int wn   = wid >> 1;       // 2 n-tiles of 64

    const __nv_bfloat16* gbase[4] = {
        Ah + (size_t)bm * D_K, Al + (size_t)bm * D_K,
        Bh + (size_t)bn * D_K, Bl + (size_t)bn * D_K };

    const int a_row = (lane & 15);
    const int a_ch  = lane >> 4;
    const uint32_t aoff = (uint32_t)((wm * 64 + a_row) * ROWB + a_ch * 16);
    const int b_row = (lane & 7) + ((lane >> 4) << 3);
    const int b_ch  = (lane >> 3) & 1;
    const uint32_t boff = (uint32_t)((wn * 64 + b_row) * ROWB + b_ch * 16);

    float acc[4][8][4];
#pragma unroll
    for (int i = 0; i < 4; i++)
#pragma unroll
        for (int j = 0; j < 8; j++)
#pragma unroll
            for (int q = 0; q < 4; q++) acc[i][j][q] = 0.f;

    auto load_stage = [&](int buf, int kc) {
        const int koff = kc * KC;
        const uint32_t sbase = sb + buf * STAGEB;
#pragma unroll
        for (int q = 0; q < 16; q++) {
            const int t   = q >> 2;                 // tile 0..3
            const int rem = ((q & 3) << 7) + tid;   // 0..511 chunk within tile
            const int row = rem >> 2;
            const int ch  = rem & 3;
            cp16(sbase + t * TILEB + row * ROWB + ch * 16,
                 gbase[t] + (size_t)row * D_K + koff + ch * 8);
        }
        CP_COMMIT();
    };

    load_stage(0, 0);

    for (int kc = 0; kc < NIT; kc++) {
        if (kc + 1 < NIT) load_stage((kc + 1) & 1, kc + 1);
        if (kc + 1 < NIT) CP_WAIT1(); else CP_WAIT0();
        __syncthreads();

        const uint32_t st = sb + (kc & 1) * STAGEB;
#pragma unroll
        for (int ks = 0; ks < 2; ks++) {
            uint32_t ah[4][4], al[4][4], bh[4][4], bl[4][4];
#pragma unroll
            for (int mf = 0; mf < 4; mf++) {
                const uint32_t ao = aoff + mf * 16 * ROWB + ks * 32;
                ldsm4(ah[mf][0], ah[mf][1], ah[mf][2], ah[mf][3], st + 0 * TILEB + ao);
                ldsm4(al[mf][0], al[mf][1], al[mf][2], al[mf][3], st + 1 * TILEB + ao);
            }
#pragma unroll
            for (int nf2 = 0; nf2 < 4; nf2++) {
                const uint32_t bo = boff + nf2 * 16 * ROWB + ks * 32;
                ldsm4(bh[nf2][0], bh[nf2][1], bh[nf2][2], bh[nf2][3], st + 2 * TILEB + bo);
                ldsm4(bl[nf2][0], bl[nf2][1], bl[nf2][2], bl[nf2][3], st + 3 * TILEB + bo);
            }
            // term-outermost: consecutive MMAs hit different accumulators
#pragma unroll
            for (int mf = 0; mf < 4; mf++)
#pragma unroll
                for (int nf = 0; nf < 8; nf++) {
                    const int h = nf >> 1, o = (nf & 1) << 1;
                    mma16816(acc[mf][nf], ah[mf], bh[h][o], bh[h][o + 1]);   // hi*hi
                }
#pragma unroll
            for (int mf = 0; mf < 4; mf++)
#pragma unroll
                for (int nf = 0; nf < 8; nf++) {
                    const int h = nf >> 1, o = (nf & 1) << 1;
                    mma16816(acc[mf][nf], ah[mf], bl[h][o], bl[h][o + 1]);   // hi*lo
                }
#pragma unroll
            for (int mf = 0; mf < 4; mf++)
#pragma unroll
                for (int nf = 0; nf < 8; nf++) {
                    const int h = nf >> 1, o = (nf & 1) << 1;
                    mma16816(acc[mf][nf], al[mf], bh[h][o], bh[h][o + 1]);   // lo*hi
                }
        }
        __syncthreads();
    }

    // epilogue: d2 = a2[m] + b2[n] - 2*dot ; mirror for cc off-diagonal tiles
#pragma unroll
    for (int mf = 0; mf < 4; mf++) {
        const int r0  = bm + wm * 64 + mf * 16 + (lane >> 2);
        const float am0 = a2[r0];
        const float am1 = a2[r0 + 8];
        float* out0 = Dout + (size_t)r0 * C_C;
        float* out1 = Dout + (size_t)(r0 + 8) * C_C;
#pragma unroll
        for (int nf = 0; nf < 8; nf++) {
            const int n = bn + wn * 64 + nf * 8 + ((lane & 3) << 1);
            const float b0 = b2[n], b1 = b2[n + 1];
            float2 p0, p1;
            p0.x = fmaf(-2.f, acc[mf][nf][0], am0 + b0);
            p0.y = fmaf(-2.f, acc[mf][nf][1], am0 + b1);
            p1.x = fmaf(-2.f, acc[mf][nf][2], am1 + b0);
            p1.y = fmaf(-2.f, acc[mf][nf][3], am1 + b1);
            *(float2*)(out0 + n) = p0;
            *(float2*)(out1 + n) = p1;
            if (mirror) {
                float* t0 = Dout + (size_t)n * C_C;
                float* t1 = Dout + (size_t)(n + 1) * C_C;
                t0[r0]     = p0.x;  t1[r0]     = p0.y;
                t0[r0 + 8] = p1.x;  t1[r0 + 8] = p1.y;
            }
        }
    }
}

// ---------------------------------------------------------------------------
// Per-center 3-NN (single pass + merge)
// ---------------------------------------------------------------------------
__global__ void near3_k() {
    const int c0  = blockIdx.x;
    const int tid = threadIdx.x;
    const float* row = g_Dcc + (size_t)c0 * C_C;

    float t0 = INFINITY, t1 = INFINITY, t2 = INFINITY;
    int   i0 = IBIG,     i1 = IBIG,     i2 = IBIG;
#pragma unroll
    for (int j = 0; j < C_C / 256; j++) {
        const int c = tid + j * 256;
        const float v = row[c];
        if (v < t2 || (v == t2 && c < i2)) {
            t2 = v; i2 = c;
            if (t2 < t1 || (t2 == t1 && i2 < i1)) {
                float tv = t1; int ti = i1; t1 = t2; i1 = i2; t2 = tv; i2 = ti;
                if (t1 < t0 || (t1 == t0 && i1 < i0)) {
                    tv = t0; ti = i0; t0 = t1; i0 = i1; t1 = tv; i1 = ti;
                }
            }
        }
    }
    __shared__ float sval[3 * 256];
    __shared__ int   sidx[3 * 256];
    sval[tid] = t0;       sidx[tid] = i0;
    sval[tid + 256] = t1; sidx[tid + 256] = i1;
    sval[tid + 512] = t2; sidx[tid + 512] = i2;
    __syncthreads();

    __shared__ float rv[256];
    __shared__ int   ri[256];
    __shared__ int   out3[3];
    for (int it = 0; it < NEARK; it++) {
        float bv = sval[tid]; int bi = sidx[tid];
#pragma unroll
        for (int k = 1; k < 3; k++) {
            float v = sval[tid + k * 256]; int ii = sidx[tid + k * 256];
            if (v < bv || (v == bv && ii < bi)) { bv = v; bi = ii; }
        }
        rv[tid] = bv; ri[tid] = bi;
        __syncthreads();
        for (int st = 128; st > 0; st >>= 1) {
            if (tid < st) {
                float v2 = rv[tid + st]; int j2 = ri[tid + st];
                if (v2 < rv[tid] || (v2 == rv[tid] && j2 < ri[tid])) { rv[tid] = v2; ri[tid] = j2; }
            }
            __syncthreads();
        }
        const float wv = rv[0]; const int wi = ri[0];
        if (tid == 0) out3[it] = wi;
#pragma unroll
        for (int k = 0; k < 3; k++) {
            if (sval[tid + k * 256] == wv && sidx[tid + k * 256] == wi) {
                sval[tid + k * 256] = INFINITY; sidx[tid + k * 256] = IBIG;
            }
        }
        __syncthreads();
    }
    if (tid == 0) { int4 p; p.x = out3[0]; p.y = out3[1]; p.z = out3[2]; p.w = 0; g_near[c0] = p; }
}

// ---------------------------------------------------------------------------
// Per-feature-row selection (non-iterative)
// ---------------------------------------------------------------------------
__global__ void select_k() {
    const int b   = blockIdx.x;
    const int l   = b / NUMR;
    const int tid = threadIdx.x;
    const float* row = g_Dfc + (size_t)b * C_C;

    float v[C_C / 256];
    float bv = INFINITY; int bi = IBIG;
#pragma unroll
    for (int j = 0; j < C_C / 256; j++) {
        const int c = tid + j * 256;
        const float d = row[c];
        v[j] = d;
        const int4 nr = g_near[c];
        const bool tr = (c != l) && (nr.x != l) && (nr.y != l) && (nr.z != l);
        if (tr && (d < bv || (d == bv && c < bi))) { bv = d; bi = c; }
    }
    __shared__ float rv[256];
    __shared__ int   ri[256];
    rv[tid] = bv; ri[tid] = bi;
    __syncthreads();
    for (int st = 128; st > 0; st >>= 1) {
        if (tid < st) {
            float v2 = rv[tid + st]; int i2 = ri[tid + st];
            if (v2 < rv[tid] || (v2 == rv[tid] && i2 < ri[tid])) { rv[tid] = v2; ri[tid] = i2; }
        }
        __syncthreads();
    }
    const float Tval = rv[0]; const int Tidx = ri[0];
    __syncthreads();

    int cnt = 0;
#pragma unroll
    for (int j = 0; j < C_C / 256; j++) {
        const int c = tid + j * 256;
        if (c != l && (v[j] < Tval || (v[j] == Tval && c < Tidx))) cnt++;
    }
    __shared__ int rc[256];
    rc[tid] = cnt;
    __syncthreads();
    for (int st = 128; st > 0; st >>= 1) { if (tid < st) rc[tid] += rc[tid + st]; __syncthreads(); }

    if (tid == 0) {
        const bool found = (Tidx < C_C) && (rc[0] <= MAXIT - 1);
        const float same = sqrtf(fmaxf(row[l], 0.f));
        const float md   = found ? sqrtf(fmaxf(Tval, 0.f)) : 0.f;
        g_hinge[b] = fmaxf(MARGINF + same - md, 0.f);
    }
}

// ---------------------------------------------------------------------------
__global__ void reduce_k(float* __restrict__ out) {
    const int tid = threadIdx.x;
    __shared__ float red[256];
    float s = 0.f;
    for (int i = tid; i < B_F; i += 256) s += g_hinge[i];
    red[tid] = s;
    __syncthreads();
    for (int st = 128; st > 0; st >>= 1) { if (tid < st) red[tid] += red[tid + st]; __syncthreads(); }
    if (tid == 0) out[0] = red[0] * (1.0f / (float)B_F);
}

// ---------------------------------------------------------------------------
extern "C" void kernel_launch(void* const* d_in, const int* in_sizes, int n_in,
                              void* d_out, int out_size) {
    (void)in_sizes; (void)n_in; (void)out_size;
    const float* feat = (const float*)d_in[0];
    const float* cent = (const float*)d_in[1];
    float* out = (float*)d_out;

    cudaFuncSetAttribute(mma_gemm_all_k, cudaFuncAttributeMaxDynamicSharedMemorySize, SMEMB);

    split_norm_all_k<<<B_F + C_C, 256>>>(feat, cent);
    mma_gemm_all_k<<<NGRID, 128, SMEMB>>>();
    near3_k<<<C_C, 256>>>();
    select_k<<<B_F, 256>>>();
    reduce_k<<<1, 256>>>(out);
}